// round 10
// baseline (speedup 1.0000x reference)
#include <cuda_runtime.h>
#include <cstdint>

typedef unsigned long long ull;
#define THREADS 512

// tile: 10 low-res rows x 14 low-res cols -> 20 x 28 outputs
// smem: xb ull  [16 ic][13 r][18]  (dup-packed x)  @ 0      = 29952 B
//       wb ull2 [16 ic][8 op][5]                   @ 29952  = 10240 B
//       z2 ull  [8 op][24 zr][34 zeta]             @ 40192  = 52224 B
#define XB_R   18
#define WB_OFF 29952
#define Z2_OFF 40192
#define Z2_ROW 34
#define Z2_OP  (24 * Z2_ROW)
#define SMEM_BYTES 92416

__device__ __forceinline__ ull pack2(float v) {
    ull r; asm("mov.b64 %0, {%1, %1};" : "=l"(r) : "f"(v)); return r;
}
__device__ __forceinline__ ull packf2(float a, float b) {
    ull r; asm("mov.b64 %0, {%1, %2};" : "=l"(r) : "f"(a), "f"(b)); return r;
}
__device__ __forceinline__ void fma2(ull &acc, ull a, ull b) {
    asm("fma.rn.f32x2 %0, %1, %2, %0;" : "+l"(acc) : "l"(a), "l"(b));
}

__global__ __launch_bounds__(THREADS, 2)
void conv_resample_v10(const float* __restrict__ x, const float* __restrict__ f,
                       const float* __restrict__ w, float* __restrict__ out) {
    extern __shared__ char sm[];
    ull* xb = (ull*)sm;
    ulonglong2* wb = (ulonglong2*)(sm + WB_OFF);
    ull* zb = (ull*)(sm + Z2_OFF);

    const int tid = threadIdx.x;
    const int wid = tid >> 5, ln = tid & 31;
    const int rt = blockIdx.x / 19, ct = blockIdx.x % 19;
    const int g = blockIdx.y, n = blockIdx.z;
    const int a0 = (rt * 10 < 246) ? rt * 10 : 246;   // clamp: overlap writes identical values
    const int b0 = (ct * 14 < 242) ? ct * 14 : 242;

    // ---- stage 1: dup-packed x tile [16 ic][13 r][17 c], zero halo ----
    const float* xg = x + ((size_t)(n * 128 + g * 16)) * 65536;
    for (int i = tid; i < 16 * 13 * 17; i += THREADS) {
        int c = i % 17;
        int rr = (i / 17) % 13;
        int ic = i / 221;
        int gm = a0 - 2 + rr, gq = b0 - 2 + c;
        float v = (gm >= 0 && gm < 256 && gq >= 0 && gq < 256)
                    ? xg[ic * 65536 + gm * 256 + gq] : 0.f;
        xb[(ic * 13 + rr) * XB_R + c] = pack2(v);
    }
    // ---- weights: oc-pair f32x2 in paired ull2 [ic][op][5]:
    //      j0=(w0,w1) j1=(w2,w6) j2=(w7,w8) j3=(w3,w5) j4=(w4,0) ----
    {
        const int lt[5] = {0, 2, 7, 3, 4};
        const int ht[5] = {1, 6, 8, 5, 0};
        const float* wgp = w + (size_t)g * 16 * 144;
        for (int i = tid; i < 16 * 8 * 5; i += THREADS) {
            int j = i % 5;
            int op = (i / 5) & 7;
            int ic = i / 40;
            const float* w0 = wgp + (op * 2 + 0) * 144 + ic * 9;
            const float* w1 = wgp + (op * 2 + 1) * 144 + ic * 9;
            ulonglong2 pr;
            pr.x = packf2(w0[lt[j]], w1[lt[j]]);
            pr.y = (j == 4) ? 0ull : packf2(w0[ht[j]], w1[ht[j]]);
            wb[i] = pr;
        }
    }
    float f0 = __ldg(f), f1 = __ldg(f + 1), f2 = __ldg(f + 2), f3 = __ldg(f + 3);
    ull gq0 = pack2(2.f * f3), gq1 = pack2(2.f * f2),
        gq2 = pack2(2.f * f1), gq3 = pack2(2.f * f0);
    __syncthreads();

    // ---- stage 2: 16 units = (4 op-groups) x (4 row-blocks of 3 pos rows) ----
    {
        const int opg = wid & 3, rb = wid >> 2;
        const int op = opg * 2 + (ln >> 4);
        const int pc = ln & 15;
        const int ar0 = rb * 3;

        ull acc[3][4];
#pragma unroll
        for (int r = 0; r < 3; ++r) { acc[r][0] = acc[r][1] = acc[r][2] = acc[r][3] = 0ull; }

#pragma unroll 4
        for (int ic = 0; ic < 16; ++ic) {
            const ulonglong2* wp = wb + (ic * 8 + op) * 5;
            ulonglong2 W0 = wp[0];   // (w0, w1)
            ulonglong2 W1 = wp[1];   // (w2, w6)
            ulonglong2 W2 = wp[2];   // (w7, w8)
            ulonglong2 W3 = wp[3];   // (w3, w5)
            ull W4 = wp[4].x;        // w4
            const ull* xr = xb + (ic * 13 + ar0) * XB_R + pc;
            ull xa = xr[0], xbv = xr[1];
#pragma unroll
            for (int r = 0; r < 3; ++r) {
                ull ya = xr[(r + 1) * XB_R];
                ull yb = xr[(r + 1) * XB_R + 1];
                fma2(acc[r][0], xa,  W0.x); fma2(acc[r][0], xbv, W1.x);
                fma2(acc[r][0], ya,  W1.y); fma2(acc[r][0], yb,  W2.y);
                fma2(acc[r][1], xbv, W0.y); fma2(acc[r][1], yb,  W2.x);
                fma2(acc[r][2], ya,  W3.x); fma2(acc[r][2], yb,  W3.y);
                fma2(acc[r][3], yb,  W4);
                xa = ya; xbv = yb;
            }
        }
        // interleaved-zeta store: zr = 2*(ar0+r)+py ; zeta = 2*pc (+1)
        ull* zo = zb + (size_t)op * Z2_OP + 2 * pc;
#pragma unroll
        for (int r = 0; r < 3; ++r) {
            int zr0 = 2 * (ar0 + r);
            ulonglong2 e0; e0.x = acc[r][0]; e0.y = acc[r][1];   // py0: (px0, px1)
            ulonglong2 e1; e1.x = acc[r][2]; e1.y = acc[r][3];   // py1
            *(ulonglong2*)(zo + (size_t)zr0 * Z2_ROW)       = e0;
            *(ulonglong2*)(zo + (size_t)(zr0 + 1) * Z2_ROW) = e1;
        }
    }
    __syncthreads();

    // ---- stage 3: vertical FIR register ring; warp = (op, row-half), lane = out col ----
    {
        const int op3 = wid & 7, rh = wid >> 3;
        const int oy0 = rh * 10;
        const bool lane_ok = (ln < 28);
        const int oxc = lane_ok ? ln : 27;

        const ull* zp = zb + (size_t)op3 * Z2_OP + (size_t)(oy0 + 1) * Z2_ROW + (oxc + 1);
        ull tb0, tb1, tb2;
        { ull t = 0; fma2(t, zp[0], gq0); fma2(t, zp[1], gq1);
          fma2(t, zp[2], gq2); fma2(t, zp[3], gq3); tb0 = t; zp += Z2_ROW; }
        { ull t = 0; fma2(t, zp[0], gq0); fma2(t, zp[1], gq1);
          fma2(t, zp[2], gq2); fma2(t, zp[3], gq3); tb1 = t; zp += Z2_ROW; }
        { ull t = 0; fma2(t, zp[0], gq0); fma2(t, zp[1], gq1);
          fma2(t, zp[2], gq2); fma2(t, zp[3], gq3); tb2 = t; zp += Z2_ROW; }

        const bool col_ok = lane_ok && (2 * b0 + ln < 512);
        float* og = out + ((size_t)(n * 128 + g * 16 + op3 * 2)) * 262144
                        + (size_t)(2 * a0) * 512 + 2 * b0;

#pragma unroll 5
        for (int oyl = 0; oyl < 10; ++oyl) {
            ull t = 0;
            fma2(t, zp[0], gq0); fma2(t, zp[1], gq1);
            fma2(t, zp[2], gq2); fma2(t, zp[3], gq3);
            zp += Z2_ROW;
            ull y = 0;
            fma2(y, tb0, gq0); fma2(y, tb1, gq1);
            fma2(y, tb2, gq2); fma2(y, t, gq3);
            tb0 = tb1; tb1 = tb2; tb2 = t;
            int oy = oy0 + oyl;
            if (col_ok) {
                float2 yy = *(float2*)&y;
                size_t o = (size_t)oy * 512 + ln;
                og[o] = yy.x;
                og[o + 262144] = yy.y;
            }
        }
    }
}

extern "C" void kernel_launch(void* const* d_in, const int* in_sizes, int n_in,
                              void* d_out, int out_size) {
    const float* x = (const float*)d_in[0];
    const float* f = (const float*)d_in[1];
    const float* w = (const float*)d_in[2];
    float* out = (float*)d_out;

    cudaFuncSetAttribute(conv_resample_v10,
                         cudaFuncAttributeMaxDynamicSharedMemorySize, SMEM_BYTES);
    dim3 grid(26 * 19, 8, 4);   // 26 row-tiles x 19 col-tiles, groups, batch
    conv_resample_v10<<<grid, THREADS, SMEM_BYTES>>>(x, f, w, out);
}

// round 11
// speedup vs baseline: 1.0088x; 1.0088x over previous
#include <cuda_runtime.h>
#include <cstdint>

typedef unsigned long long ull;
#define THREADS 512

// tile: 6 low-res rows x 14 low-res cols -> 12 x 28 outputs, batch-PAIR packed f32x2
// smem:
//   xb ull  [16 ic][9 r][18 c]    @ 0      = 20736 B  (x (n0,n1) packed)
//   wb ull  [16 ic][16 oc][10 t]  @ 20736  = 20480 B  (dup-packed weights)
//   z2 ull  [16 oc][16 zr][34 z]  @ 41216  = 69632 B  (batch-pair valued)
#define XB_R   18
#define WB_OFF 20736
#define Z2_OFF 41216
#define Z2_ROW 34
#define Z2_OC  (16 * Z2_ROW)
#define SMEM_BYTES 110848

__device__ __forceinline__ ull pack2(float v) {
    ull r; asm("mov.b64 %0, {%1, %1};" : "=l"(r) : "f"(v)); return r;
}
__device__ __forceinline__ ull packf2(float a, float b) {
    ull r; asm("mov.b64 %0, {%1, %2};" : "=l"(r) : "f"(a), "f"(b)); return r;
}
__device__ __forceinline__ void fma2(ull &acc, ull a, ull b) {
    asm("fma.rn.f32x2 %0, %1, %2, %0;" : "+l"(acc) : "l"(a), "l"(b));
}

__global__ __launch_bounds__(THREADS, 2)
void conv_resample_v11(const float* __restrict__ x, const float* __restrict__ f,
                       const float* __restrict__ w, float* __restrict__ out) {
    extern __shared__ char sm[];
    ull* xb = (ull*)sm;
    ull* wb = (ull*)(sm + WB_OFF);
    ull* zb = (ull*)(sm + Z2_OFF);

    const int tid = threadIdx.x;
    const int wid = tid >> 5, ln = tid & 31;
    const int rt = blockIdx.x / 19, ct = blockIdx.x % 19;
    const int g = blockIdx.y;
    const int n0 = blockIdx.z * 2;                 // batch pair (n0, n0+1)
    const int a0 = (rt * 6 < 250) ? rt * 6 : 250;  // clamped tiles overlap-write identical values
    const int b0 = (ct * 14 < 242) ? ct * 14 : 242;

    // ---- stage 1: batch-pair packed x tile [16 ic][9 r][17 c], zero halo ----
    const float* xg0 = x + ((size_t)(n0 * 128 + g * 16)) * 65536;
    const float* xg1 = xg0 + (size_t)128 * 65536;
    for (int i = tid; i < 16 * 9 * 17; i += THREADS) {
        int c = i % 17;
        int rr = (i / 17) % 9;
        int ic = i / 153;
        int gm = a0 - 2 + rr, gq = b0 - 2 + c;
        ull v = 0ull;
        if (gm >= 0 && gm < 256 && gq >= 0 && gq < 256) {
            size_t off = (size_t)ic * 65536 + gm * 256 + gq;
            v = packf2(xg0[off], xg1[off]);
        }
        xb[(ic * 9 + rr) * XB_R + c] = v;
    }
    // ---- weights dup-packed: [ic][oc][10] (tap 9 = pad) ----
    {
        const float* wgp = w + (size_t)g * 16 * 144;
        for (int i = tid; i < 16 * 16 * 10; i += THREADS) {
            int t = i % 10;
            int oc = (i / 10) & 15;
            int ic = i / 160;
            wb[i] = (t < 9) ? pack2(wgp[oc * 144 + ic * 9 + t]) : 0ull;
        }
    }
    float f0 = __ldg(f), f1 = __ldg(f + 1), f2 = __ldg(f + 2), f3 = __ldg(f + 3);
    ull gq0 = pack2(2.f * f3), gq1 = pack2(2.f * f2),
        gq2 = pack2(2.f * f1), gq3 = pack2(2.f * f0);
    __syncthreads();

    // ---- stage 2: warp = oc; lane = (row-block rb, pos col c); 4 pos rows per rb ----
    {
        const int oc = wid;
        const int c = ln & 15, rb = ln >> 4;
        const int pr0 = rb * 4;

        ull acc[4][4];
#pragma unroll
        for (int r = 0; r < 4; ++r)
            acc[r][0] = acc[r][1] = acc[r][2] = acc[r][3] = 0ull;

#pragma unroll 2
        for (int ic = 0; ic < 16; ++ic) {
            const ull* wp = wb + (ic * 16 + oc) * 10;
            ulonglong2 W01 = *(const ulonglong2*)(wp);       // (w0,w1)
            ulonglong2 W23 = *(const ulonglong2*)(wp + 2);   // (w2,w3)
            ulonglong2 W45 = *(const ulonglong2*)(wp + 4);   // (w4,w5)
            ulonglong2 W67 = *(const ulonglong2*)(wp + 6);   // (w6,w7)
            ull w8 = wp[8];
            const ull* xr = xb + (ic * 9 + pr0) * XB_R + c;
            ull xa = xr[0], xbv = xr[1];
#pragma unroll
            for (int r = 0; r < 4; ++r) {
                ull ya = xr[(r + 1) * XB_R];
                ull yb = xr[(r + 1) * XB_R + 1];
                fma2(acc[r][0], xa,  W01.x); fma2(acc[r][0], xbv, W23.x);
                fma2(acc[r][0], ya,  W67.x); fma2(acc[r][0], yb,  w8);
                fma2(acc[r][1], xbv, W01.y); fma2(acc[r][1], yb,  W67.y);
                fma2(acc[r][2], ya,  W23.y); fma2(acc[r][2], yb,  W45.y);
                fma2(acc[r][3], yb,  W45.x);
                xa = ya; xbv = yb;
            }
        }
        // z2 store: zr = 2*(pr0+r)+py, zeta = 2*c+px
        ull* zo = zb + (size_t)oc * Z2_OC + 2 * c;
#pragma unroll
        for (int r = 0; r < 4; ++r) {
            int zr0 = 2 * (pr0 + r);
            ulonglong2 e0; e0.x = acc[r][0]; e0.y = acc[r][1];   // py0: (px0,px1)
            ulonglong2 e1; e1.x = acc[r][2]; e1.y = acc[r][3];   // py1
            *(ulonglong2*)(zo + (size_t)zr0 * Z2_ROW)       = e0;
            *(ulonglong2*)(zo + (size_t)(zr0 + 1) * Z2_ROW) = e1;
        }
    }
    __syncthreads();

    // ---- stage 3: vertical FIR register ring; warp = oc, lane = output col ----
    {
        const int oc = wid;
        const bool lane_ok = (ln < 28);
        const int ox = lane_ok ? ln : 27;

        const ull* zp = zb + (size_t)oc * Z2_OC + Z2_ROW + (ox + 1);
        ull tb0, tb1, tb2;
        { ull t = 0; fma2(t, zp[0], gq0); fma2(t, zp[1], gq1);
          fma2(t, zp[2], gq2); fma2(t, zp[3], gq3); tb0 = t; zp += Z2_ROW; }
        { ull t = 0; fma2(t, zp[0], gq0); fma2(t, zp[1], gq1);
          fma2(t, zp[2], gq2); fma2(t, zp[3], gq3); tb1 = t; zp += Z2_ROW; }
        { ull t = 0; fma2(t, zp[0], gq0); fma2(t, zp[1], gq1);
          fma2(t, zp[2], gq2); fma2(t, zp[3], gq3); tb2 = t; zp += Z2_ROW; }

        float* og0 = out + ((size_t)(n0 * 128 + g * 16 + oc)) * 262144
                         + (size_t)(2 * a0) * 512 + 2 * b0 + ox;
        float* og1 = og0 + (size_t)128 * 262144;

#pragma unroll 6
        for (int oy = 0; oy < 12; ++oy) {
            ull t = 0;
            fma2(t, zp[0], gq0); fma2(t, zp[1], gq1);
            fma2(t, zp[2], gq2); fma2(t, zp[3], gq3);
            zp += Z2_ROW;
            ull y = 0;
            fma2(y, tb0, gq0); fma2(y, tb1, gq1);
            fma2(y, tb2, gq2); fma2(y, t, gq3);
            tb0 = tb1; tb1 = tb2; tb2 = t;
            if (lane_ok) {
                float2 yy = *(float2*)&y;
                size_t o = (size_t)oy * 512;
                og0[o] = yy.x;      // batch n0
                og1[o] = yy.y;      // batch n0+1
            }
        }
    }
}

extern "C" void kernel_launch(void* const* d_in, const int* in_sizes, int n_in,
                              void* d_out, int out_size) {
    const float* x = (const float*)d_in[0];
    const float* f = (const float*)d_in[1];
    const float* w = (const float*)d_in[2];
    float* out = (float*)d_out;

    cudaFuncSetAttribute(conv_resample_v11,
                         cudaFuncAttributeMaxDynamicSharedMemorySize, SMEM_BYTES);
    dim3 grid(43 * 19, 8, 2);   // (row-tiles x col-tiles, groups, batch-pairs)
    conv_resample_v11<<<grid, THREADS, SMEM_BYTES>>>(x, f, w, out);
}

// round 12
// speedup vs baseline: 1.0585x; 1.0492x over previous
#include <cuda_runtime.h>
#include <cstdint>

typedef unsigned long long ull;
#define THREADS 512

// tile: 14x14 low-res -> 28x28 output
// smem: xb float [16 ic][17 r][18 pad]        @ 0      = 19584 B
//       wb ull2  [16 ic][8 op][5 pairs]       @ 19584  = 10240 B
//       z2 ull   [8 op][32 zr][36 (zeta,pad)] @ 29824  = 73728 B
#define XB_R   18
#define WB_OFF 19584
#define Z2_OFF 29824
#define Z2_ROW 36
#define Z2_OP  (32 * Z2_ROW)
#define SMEM_BYTES 103552

__device__ __forceinline__ ull pack2(float v) {
    ull r; asm("mov.b64 %0, {%1, %1};" : "=l"(r) : "f"(v)); return r;
}
__device__ __forceinline__ ull packf2(float a, float b) {
    ull r; asm("mov.b64 %0, {%1, %2};" : "=l"(r) : "f"(a), "f"(b)); return r;
}
__device__ __forceinline__ void fma2(ull &acc, ull a, ull b) {
    asm("fma.rn.f32x2 %0, %1, %2, %0;" : "+l"(acc) : "l"(a), "l"(b));
}

__global__ __launch_bounds__(THREADS, 2)
void conv_resample_v12(const float* __restrict__ x, const float* __restrict__ f,
                       const float* __restrict__ w, float* __restrict__ out) {
    extern __shared__ char sm[];
    float* xb = (float*)sm;
    ulonglong2* wb = (ulonglong2*)(sm + WB_OFF);
    ull* zb = (ull*)(sm + Z2_OFF);

    const int tid = threadIdx.x;
    const int wid = tid >> 5, ln = tid & 31;
    const int rt = blockIdx.x / 19, ct = blockIdx.x % 19;
    const int g = blockIdx.y, n = blockIdx.z;
    const int a0 = rt * 14, b0 = ct * 14;

    // ---- stage 1: x tile [16 ic][17][17] with zero halo ----
    const float* xg = x + ((size_t)(n * 128 + g * 16)) * 65536;
    for (int i = tid; i < 16 * 17 * 17; i += THREADS) {
        int c = i % 17;
        int rr = (i / 17) % 17;
        int ic = i / 289;
        int gm = a0 - 2 + rr, gq = b0 - 2 + c;
        float v = (gm >= 0 && gm < 256 && gq >= 0 && gq < 256)
                    ? xg[ic * 65536 + gm * 256 + gq] : 0.f;
        xb[(ic * 17 + rr) * XB_R + c] = v;
    }
    // ---- weights: oc-pair f32x2 in paired ull2 [ic][op][5]:
    //      j0=(w0,w1) j1=(w2,w6) j2=(w7,w8) j3=(w3,w5) j4=(w4,0) ----
    {
        const int lt[5] = {0, 2, 7, 3, 4};
        const int ht[5] = {1, 6, 8, 5, 0};
        const float* wgp = w + (size_t)g * 16 * 144;
        for (int i = tid; i < 16 * 8 * 5; i += THREADS) {
            int j = i % 5;
            int op = (i / 5) & 7;
            int ic = i / 40;
            const float* w0 = wgp + (op * 2 + 0) * 144 + ic * 9;
            const float* w1 = wgp + (op * 2 + 1) * 144 + ic * 9;
            ulonglong2 pr;
            pr.x = packf2(w0[lt[j]], w1[lt[j]]);
            pr.y = (j == 4) ? 0ull : packf2(w0[ht[j]], w1[ht[j]]);
            wb[i] = pr;
        }
    }
    float f0 = __ldg(f), f1 = __ldg(f + 1), f2 = __ldg(f + 2), f3 = __ldg(f + 3);
    ull gq0 = pack2(2.f * f3), gq1 = pack2(2.f * f2),
        gq2 = pack2(2.f * f1), gq3 = pack2(2.f * f0);
    __syncthreads();

    // ---- stage 2: 16 units = (4 op-groups) x (4 row-blocks); lane = (op-half, 16 cols) ----
    {
        const int opg = wid & 3, rb = wid >> 2;
        const int op = opg * 2 + (ln >> 4);
        const int pc = ln & 15;
        const int ar0 = rb * 4;

        ull acc[4][4];
#pragma unroll
        for (int r = 0; r < 4; ++r) { acc[r][0] = acc[r][1] = acc[r][2] = acc[r][3] = 0ull; }

#pragma unroll 4
        for (int ic = 0; ic < 16; ++ic) {
            const ulonglong2* wp = wb + (ic * 8 + op) * 5;
            ulonglong2 W0 = wp[0];   // (w0, w1)
            ulonglong2 W1 = wp[1];   // (w2, w6)
            ulonglong2 W2 = wp[2];   // (w7, w8)
            ulonglong2 W3 = wp[3];   // (w3, w5)
            ull W4 = wp[4].x;        // w4
            const float* xr = xb + (ic * 17 + ar0) * XB_R + pc;
            ull xa = pack2(xr[0]), xbv = pack2(xr[1]);
#pragma unroll
            for (int r = 0; r < 4; ++r) {
                ull ya = pack2(xr[(r + 1) * XB_R]);
                ull yb = pack2(xr[(r + 1) * XB_R + 1]);
                fma2(acc[r][0], xa,  W0.x); fma2(acc[r][0], xbv, W1.x);
                fma2(acc[r][0], ya,  W1.y); fma2(acc[r][0], yb,  W2.y);
                fma2(acc[r][1], xbv, W0.y); fma2(acc[r][1], yb,  W2.x);
                fma2(acc[r][2], ya,  W3.x); fma2(acc[r][2], yb,  W3.y);
                fma2(acc[r][3], yb,  W4);
                xa = ya; xbv = yb;
            }
        }
        // interleaved-zeta store: zr = 2*(ar0+r)+py ; zeta = 2*pc (+1)
        ull* zo = zb + (size_t)op * Z2_OP + 2 * pc;
#pragma unroll
        for (int r = 0; r < 4; ++r) {
            int zr0 = 2 * (ar0 + r);
            ulonglong2 e0; e0.x = acc[r][0]; e0.y = acc[r][1];   // py0: (px0, px1)
            ulonglong2 e1; e1.x = acc[r][2]; e1.y = acc[r][3];   // py1
            *(ulonglong2*)(zo + (size_t)zr0 * Z2_ROW)       = e0;
            *(ulonglong2*)(zo + (size_t)(zr0 + 1) * Z2_ROW) = e1;
        }
    }
    __syncthreads();

    // ---- stage 3: vertical FIR, 2 output cols per lane via LDS.128 ----
    // warp = (op, row-half); half-warp h covers 7 output rows; lane m -> cols 2m, 2m+1
    {
        const int op3 = wid & 7, rh = wid >> 3;
        const int h = ln >> 4, m = ln & 15;
        const int oyb = rh * 14 + h * 7;          // this half-warp's first output row
        const bool lane_ok = (m < 14);
        const int mm = lane_ok ? m : 13;

        const ull* zcol = zb + (size_t)op3 * Z2_OP + 2 * mm;
        ull t0r[3], t1r[3];
#pragma unroll
        for (int j = 0; j < 3; ++j) {
            const ull* zp = zcol + (size_t)(oyb + 1 + j) * Z2_ROW;
            ulonglong2 zA = *(const ulonglong2*)(zp);       // zeta 2m, 2m+1
            ulonglong2 zB = *(const ulonglong2*)(zp + 2);   // zeta 2m+2, 2m+3
            ulonglong2 zC = *(const ulonglong2*)(zp + 4);   // zeta 2m+4, 2m+5
            ull t0 = 0, t1 = 0;
            fma2(t0, zA.y, gq0); fma2(t0, zB.x, gq1); fma2(t0, zB.y, gq2); fma2(t0, zC.x, gq3);
            fma2(t1, zB.x, gq0); fma2(t1, zB.y, gq1); fma2(t1, zC.x, gq2); fma2(t1, zC.y, gq3);
            t0r[j] = t0; t1r[j] = t1;
        }

        const bool col_ok = lane_ok && (2 * b0 + 2 * m < 512);
        float* og = out + ((size_t)(n * 128 + g * 16 + op3 * 2)) * 262144
                        + 2 * b0 + 2 * mm;

#pragma unroll
        for (int i = 0; i < 7; ++i) {
            const ull* zp = zcol + (size_t)(oyb + 4 + i) * Z2_ROW;
            ulonglong2 zA = *(const ulonglong2*)(zp);
            ulonglong2 zB = *(const ulonglong2*)(zp + 2);
            ulonglong2 zC = *(const ulonglong2*)(zp + 4);
            ull t0 = 0, t1 = 0;
            fma2(t0, zA.y, gq0); fma2(t0, zB.x, gq1); fma2(t0, zB.y, gq2); fma2(t0, zC.x, gq3);
            fma2(t1, zB.x, gq0); fma2(t1, zB.y, gq1); fma2(t1, zC.x, gq2); fma2(t1, zC.y, gq3);

            ull y0 = 0, y1 = 0;
            fma2(y0, t0r[0], gq0); fma2(y0, t0r[1], gq1); fma2(y0, t0r[2], gq2); fma2(y0, t0, gq3);
            fma2(y1, t1r[0], gq0); fma2(y1, t1r[1], gq1); fma2(y1, t1r[2], gq2); fma2(y1, t1, gq3);
            t0r[0] = t0r[1]; t0r[1] = t0r[2]; t0r[2] = t0;
            t1r[0] = t1r[1]; t1r[1] = t1r[2]; t1r[2] = t1;

            int oy = oyb + i;
            int gy = 2 * a0 + oy;
            if (col_ok && gy < 512) {
                float2 q0 = *(float2*)&y0;     // (oc0, oc1) at col 2m
                float2 q1 = *(float2*)&y1;     // (oc0, oc1) at col 2m+1
                float* prow = og + (size_t)gy * 512;
                *(float2*)prow = make_float2(q0.x, q1.x);             // oc even plane
                *(float2*)(prow + 262144) = make_float2(q0.y, q1.y);  // oc odd plane
            }
        }
    }
}

extern "C" void kernel_launch(void* const* d_in, const int* in_sizes, int n_in,
                              void* d_out, int out_size) {
    const float* x = (const float*)d_in[0];
    const float* f = (const float*)d_in[1];
    const float* w = (const float*)d_in[2];
    float* out = (float*)d_out;

    cudaFuncSetAttribute(conv_resample_v12,
                         cudaFuncAttributeMaxDynamicSharedMemorySize, SMEM_BYTES);
    dim3 grid(19 * 19, 8, 4);   // 361 tiles x groups x batch = 11552 CTAs
    conv_resample_v12<<<grid, THREADS, SMEM_BYTES>>>(x, f, w, out);
}

// round 13
// speedup vs baseline: 1.1623x; 1.0980x over previous
#include <cuda_runtime.h>
#include <cstdint>

typedef unsigned long long ull;
#define THREADS 512

// tile: 14x14 low-res -> 28x28 output (v9 structure, persistent CTAs)
// smem: xb float [16 ic][17 r][18 pad]        @ 0      = 19584 B
//       wb ull2  [16 ic][8 op][5 pairs]       @ 19584  = 10240 B
//       z2 ull   [8 op][32 zr][36 (zeta,pad)] @ 29824  = 73728 B
#define XB_R   18
#define WB_OFF 19584
#define Z2_OFF 29824
#define Z2_ROW 36
#define Z2_OP  (32 * Z2_ROW)
#define SMEM_BYTES 103552

#define NTILES 1444        // 4 batch * 361 spatial
#define NSLOTS 37          // CTAs per group (296 = 8 groups * 37)

__device__ __forceinline__ ull pack2(float v) {
    ull r; asm("mov.b64 %0, {%1, %1};" : "=l"(r) : "f"(v)); return r;
}
__device__ __forceinline__ ull packf2(float a, float b) {
    ull r; asm("mov.b64 %0, {%1, %2};" : "=l"(r) : "f"(a), "f"(b)); return r;
}
__device__ __forceinline__ void fma2(ull &acc, ull a, ull b) {
    asm("fma.rn.f32x2 %0, %1, %2, %0;" : "+l"(acc) : "l"(a), "l"(b));
}

__global__ __launch_bounds__(THREADS, 2)
void conv_resample_v13(const float* __restrict__ x, const float* __restrict__ f,
                       const float* __restrict__ w, float* __restrict__ out) {
    extern __shared__ char sm[];
    float* xb = (float*)sm;
    ulonglong2* wb = (ulonglong2*)(sm + WB_OFF);
    ull* zb = (ull*)(sm + Z2_OFF);

    const int tid = threadIdx.x;
    const int wid = tid >> 5, ln = tid & 31;
    const int g = blockIdx.x & 7;
    const int slot = blockIdx.x >> 3;

    // ---- one-time: weights as oc-pair f32x2 in paired ull2 [ic][op][5]:
    //      j0=(w0,w1) j1=(w2,w6) j2=(w7,w8) j3=(w3,w5) j4=(w4,0) ----
    {
        const int lt[5] = {0, 2, 7, 3, 4};
        const int ht[5] = {1, 6, 8, 5, 0};
        const float* wgp = w + (size_t)g * 16 * 144;
        for (int i = tid; i < 16 * 8 * 5; i += THREADS) {
            int j = i % 5;
            int op = (i / 5) & 7;
            int ic = i / 40;
            const float* w0 = wgp + (op * 2 + 0) * 144 + ic * 9;
            const float* w1 = wgp + (op * 2 + 1) * 144 + ic * 9;
            ulonglong2 pr;
            pr.x = packf2(w0[lt[j]], w1[lt[j]]);
            pr.y = (j == 4) ? 0ull : packf2(w0[ht[j]], w1[ht[j]]);
            wb[i] = pr;
        }
    }
    const float f0 = __ldg(f), f1 = __ldg(f + 1), f2 = __ldg(f + 2), f3 = __ldg(f + 3);
    const ull gq0 = pack2(2.f * f3), gq1 = pack2(2.f * f2),
              gq2 = pack2(2.f * f1), gq3 = pack2(2.f * f0);

    // ---- persistent tile loop ----
#pragma unroll 1
    for (int t = slot; t < NTILES; t += NSLOTS) {
        const int n = t / 361;
        const int sp = t - n * 361;
        const int rt = sp / 19, ct = sp - rt * 19;
        const int a0 = rt * 14, b0 = ct * 14;

        // ---- stage 1: x tile [16 ic][17][17] with zero halo ----
        const float* xg = x + ((size_t)(n * 128 + g * 16)) * 65536;
        for (int i = tid; i < 16 * 17 * 17; i += THREADS) {
            int c = i % 17;
            int rr = (i / 17) % 17;
            int ic = i / 289;
            int gm = a0 - 2 + rr, gq = b0 - 2 + c;
            float v = (gm >= 0 && gm < 256 && gq >= 0 && gq < 256)
                        ? xg[ic * 65536 + gm * 256 + gq] : 0.f;
            xb[(ic * 17 + rr) * XB_R + c] = v;
        }
        __syncthreads();

        // ---- stage 2: 16 units = (4 op-groups) x (4 row-blocks); lane = (op-half, 16 cols) ----
        {
            const int opg = wid & 3, rb = wid >> 2;
            const int op = opg * 2 + (ln >> 4);
            const int pc = ln & 15;
            const int ar0 = rb * 4;

            ull acc[4][4];
#pragma unroll
            for (int r = 0; r < 4; ++r) { acc[r][0] = acc[r][1] = acc[r][2] = acc[r][3] = 0ull; }

#pragma unroll 4
            for (int ic = 0; ic < 16; ++ic) {
                const ulonglong2* wp = wb + (ic * 8 + op) * 5;
                ulonglong2 W0 = wp[0];   // (w0, w1)
                ulonglong2 W1 = wp[1];   // (w2, w6)
                ulonglong2 W2 = wp[2];   // (w7, w8)
                ulonglong2 W3 = wp[3];   // (w3, w5)
                ull W4 = wp[4].x;        // w4
                const float* xr = xb + (ic * 17 + ar0) * XB_R + pc;
                ull xa = pack2(xr[0]), xbv = pack2(xr[1]);
#pragma unroll
                for (int r = 0; r < 4; ++r) {
                    ull ya = pack2(xr[(r + 1) * XB_R]);
                    ull yb = pack2(xr[(r + 1) * XB_R + 1]);
                    fma2(acc[r][0], xa,  W0.x); fma2(acc[r][0], xbv, W1.x);
                    fma2(acc[r][0], ya,  W1.y); fma2(acc[r][0], yb,  W2.y);
                    fma2(acc[r][1], xbv, W0.y); fma2(acc[r][1], yb,  W2.x);
                    fma2(acc[r][2], ya,  W3.x); fma2(acc[r][2], yb,  W3.y);
                    fma2(acc[r][3], yb,  W4);
                    xa = ya; xbv = yb;
                }
            }
            // interleaved-zeta store: zr = 2*(ar0+r)+py ; zeta = 2*pc (+1)
            ull* zo = zb + (size_t)op * Z2_OP + 2 * pc;
#pragma unroll
            for (int r = 0; r < 4; ++r) {
                int zr0 = 2 * (ar0 + r);
                ulonglong2 e0; e0.x = acc[r][0]; e0.y = acc[r][1];   // py0: (px0, px1)
                ulonglong2 e1; e1.x = acc[r][2]; e1.y = acc[r][3];   // py1
                *(ulonglong2*)(zo + (size_t)zr0 * Z2_ROW)       = e0;
                *(ulonglong2*)(zo + (size_t)(zr0 + 1) * Z2_ROW) = e1;
            }
        }
        __syncthreads();

        // ---- stage 3: vertical FIR register ring; warp = (op, row-half), lane = out col ----
        {
            const int op3 = wid & 7, rh = wid >> 3;
            const int oy0 = rh * 14;
            const bool lane_ok = (ln < 28);
            const int oxc = lane_ok ? ln : 27;

            const ull* zp = zb + (size_t)op3 * Z2_OP + (size_t)(oy0 + 1) * Z2_ROW + (oxc + 1);
            ull tb0, tb1, tb2;
            { ull tt = 0; fma2(tt, zp[0], gq0); fma2(tt, zp[1], gq1);
              fma2(tt, zp[2], gq2); fma2(tt, zp[3], gq3); tb0 = tt; zp += Z2_ROW; }
            { ull tt = 0; fma2(tt, zp[0], gq0); fma2(tt, zp[1], gq1);
              fma2(tt, zp[2], gq2); fma2(tt, zp[3], gq3); tb1 = tt; zp += Z2_ROW; }
            { ull tt = 0; fma2(tt, zp[0], gq0); fma2(tt, zp[1], gq1);
              fma2(tt, zp[2], gq2); fma2(tt, zp[3], gq3); tb2 = tt; zp += Z2_ROW; }

            const bool col_ok = lane_ok && (2 * b0 + ln < 512);
            float* og = out + ((size_t)(n * 128 + g * 16 + op3 * 2)) * 262144
                            + (size_t)(2 * a0) * 512 + 2 * b0;

#pragma unroll 7
            for (int oyl = 0; oyl < 14; ++oyl) {
                ull tt = 0;
                fma2(tt, zp[0], gq0); fma2(tt, zp[1], gq1);
                fma2(tt, zp[2], gq2); fma2(tt, zp[3], gq3);
                zp += Z2_ROW;
                ull y = 0;
                fma2(y, tb0, gq0); fma2(y, tb1, gq1);
                fma2(y, tb2, gq2); fma2(y, tt, gq3);
                tb0 = tb1; tb1 = tb2; tb2 = tt;
                int oy = oy0 + oyl;
                if (col_ok && (2 * a0 + oy < 512)) {
                    float2 yy = *(float2*)&y;
                    size_t o = (size_t)oy * 512 + ln;
                    og[o] = yy.x;
                    og[o + 262144] = yy.y;
                }
            }
        }
        __syncthreads();   // protect xb (next stage1) and zb (next stage2)
    }
}

extern "C" void kernel_launch(void* const* d_in, const int* in_sizes, int n_in,
                              void* d_out, int out_size) {
    const float* x = (const float*)d_in[0];
    const float* f = (const float*)d_in[1];
    const float* w = (const float*)d_in[2];
    float* out = (float*)d_out;

    cudaFuncSetAttribute(conv_resample_v13,
                         cudaFuncAttributeMaxDynamicSharedMemorySize, SMEM_BYTES);
    conv_resample_v13<<<296, THREADS, SMEM_BYTES>>>(x, f, w, out);   // 2 CTAs/SM, persistent
}